// round 5
// baseline (speedup 1.0000x reference)
#include <cuda_runtime.h>

#define Nn  50000
#define HID 64
#define Ee  800000
#define EPn 100000
#define BN_EPS 1e-5f
#define RPAD 132

typedef unsigned long long u64;

// ---------------- scratch ----------------
__device__ float g_x[Nn * HID];
__device__ float g_h[Nn * HID];
__device__ float g_agg[Nn * HID];
__device__ float g_dis[Nn];
__device__ float g_stats[4 * HID];   // [l0 sum | l0 sumsq | l1 sum | l1 sumsq]

// packed fp32x2 helpers (sm_100+)
#define PK(d,x,y)   asm("mov.b64 %0, {%1,%2};" : "=l"(d) : "f"(x), "f"(y))
#define UPK(x,y,d)  asm("mov.b64 {%0,%1}, %2;" : "=f"(x), "=f"(y) : "l"(d))
#define FMA2(a,b,c) asm("fma.rn.f32x2 %0, %1, %2, %0;" : "+l"(a) : "l"(b), "l"(c))

// ---------------- degree / init ----------------
__global__ void k_deg_init() {
    int i = blockIdx.x * blockDim.x + threadIdx.x;
    if (i < 4 * HID) g_stats[i] = 0.f;
    if (i < Nn) g_dis[i] = 1.0f;   // self-loop
}

__global__ void k_deg_count(const int* __restrict__ col) {
    int e = blockIdx.x * blockDim.x + threadIdx.x;
    if (e < Ee) atomicAdd(&g_dis[col[e]], 1.0f);
}

__global__ void k_deg_rsqrt() {
    int i = blockIdx.x * blockDim.x + threadIdx.x;
    if (i < Nn) g_dis[i] = rsqrtf(g_dis[i]);
}

// ---------------- GEMM pieces (128-row tiles, 256 threads, 8x4 per thread) ----
// A tile transposed: row r, col k at sa[k*RPAD + (r ^ (k&28))].
// W stored duplicated: swd[k*128 + 2c] = swd[k*128 + 2c+1] = w[k][c], so packed
// dup operands come straight out of LDS.128.

__device__ __forceinline__ void load_AT(float* sa, const float* __restrict__ g,
                                        int rb, int tid) {
    for (int i = tid; i < 2048; i += 256) {
        int r = i >> 4, kq = (i & 15) << 2;
        int row = rb * 128 + r;
        float4 v = make_float4(0.f, 0.f, 0.f, 0.f);
        if (row < Nn) v = *reinterpret_cast<const float4*>(g + row * 64 + kq);
        int p = r ^ (kq & 28);
        sa[(kq + 0) * RPAD + p] = v.x;
        sa[(kq + 1) * RPAD + p] = v.y;
        sa[(kq + 2) * RPAD + p] = v.z;
        sa[(kq + 3) * RPAD + p] = v.w;
    }
}

__device__ __forceinline__ void load_Wdup(float* swd, const float* __restrict__ w, int tid) {
    const float4* w4 = reinterpret_cast<const float4*>(w);
    for (int i = tid; i < 1024; i += 256) {
        int k = i >> 4, cq = (i & 15) << 2;
        float4 v = w4[i];
        float4* dst = reinterpret_cast<float4*>(&swd[k * 128 + cq * 2]);
        dst[0] = make_float4(v.x, v.x, v.y, v.y);
        dst[1] = make_float4(v.z, v.z, v.w, v.w);
    }
}

__device__ __forceinline__ void zero_acc(u64 acc[4][4]) {
#pragma unroll
    for (int c = 0; c < 4; c++)
#pragma unroll
        for (int p = 0; p < 4; p++) acc[c][p] = 0ull;
}

// acc[c][p]: column tc*4+c, row-pair (tr*8+2p, tr*8+2p+1)
__device__ __forceinline__ void mm128(const float* sa, const float* swd,
                                      int tc, int tr, u64 acc[4][4]) {
#pragma unroll 4
    for (int k = 0; k < 64; k++) {
        int m = k & 28;
        int p0 = (tr * 8) ^ m;
        float4 av0 = *reinterpret_cast<const float4*>(&sa[k * RPAD + p0]);
        float4 av1 = *reinterpret_cast<const float4*>(&sa[k * RPAD + (p0 ^ 4)]);
        const float4* wp = reinterpret_cast<const float4*>(&swd[k * 128 + tc * 8]);
        float4 wA = wp[0], wB = wp[1];
        u64 a[4], w[4];
        PK(a[0], av0.x, av0.y); PK(a[1], av0.z, av0.w);
        PK(a[2], av1.x, av1.y); PK(a[3], av1.z, av1.w);
        PK(w[0], wA.x, wA.y);   PK(w[1], wA.z, wA.w);
        PK(w[2], wB.x, wB.y);   PK(w[3], wB.z, wB.w);
#pragma unroll
        for (int c = 0; c < 4; c++)
#pragma unroll
            for (int p = 0; p < 4; p++)
                FMA2(acc[c][p], a[p], w[c]);
    }
}

// epilogue: write h and agg = cb + d^2 * h  (g_dis already holds d^{-1/2})
__device__ __forceinline__ void epi_h_agg(u64 acc[4][4], const float* __restrict__ cb,
                                          int rb, int tc, int tr) {
    float4 cbv = reinterpret_cast<const float4*>(cb)[tc];
#pragma unroll
    for (int p = 0; p < 4; p++) {
        float h0[4], h1[4];
#pragma unroll
        for (int c = 0; c < 4; c++) UPK(h0[c], h1[c], acc[c][p]);
        int r0 = rb * 128 + tr * 8 + 2 * p;
        if (r0 < Nn) {
            float d = g_dis[r0], d2 = d * d;
            *reinterpret_cast<float4*>(&g_h[r0 * 64 + tc * 4]) =
                make_float4(h0[0], h0[1], h0[2], h0[3]);
            *reinterpret_cast<float4*>(&g_agg[r0 * 64 + tc * 4]) =
                make_float4(cbv.x + d2 * h0[0], cbv.y + d2 * h0[1],
                            cbv.z + d2 * h0[2], cbv.w + d2 * h0[3]);
        }
        int r1 = r0 + 1;
        if (r1 < Nn) {
            float d = g_dis[r1], d2 = d * d;
            *reinterpret_cast<float4*>(&g_h[r1 * 64 + tc * 4]) =
                make_float4(h1[0], h1[1], h1[2], h1[3]);
            *reinterpret_cast<float4*>(&g_agg[r1 * 64 + tc * 4]) =
                make_float4(cbv.x + d2 * h1[0], cbv.y + d2 * h1[1],
                            cbv.z + d2 * h1[2], cbv.w + d2 * h1[3]);
        }
    }
}

// ---------------- fused proj + conv0 + agg-init ----------------
__global__ __launch_bounds__(256) void k_proj_gemm0(
    const float* __restrict__ id_emb, const float* __restrict__ n2v,
    const float* __restrict__ pw, const float* __restrict__ pb,
    const float* __restrict__ cw0, const float* __restrict__ cb0)
{
    extern __shared__ float dsm[];
    float* sa  = dsm;                 // 64 * RPAD floats
    float* swd = dsm + 64 * RPAD;     // 64 * 128 floats
    const int tid = threadIdx.x, rb = blockIdx.x;
    const int tc = tid & 15, tr = tid >> 4;

    u64 acc[4][4];
    zero_acc(acc);

    // proj phase 0: id_emb @ pw[0:64,:]
    load_AT(sa, id_emb, rb, tid);
    load_Wdup(swd, pw, tid);
    __syncthreads();
    mm128(sa, swd, tc, tr, acc);
    __syncthreads();

    // proj phase 1: n2v @ pw[64:128,:]
    load_AT(sa, n2v, rb, tid);
    load_Wdup(swd, pw + 64 * 64, tid);
    __syncthreads();
    mm128(sa, swd, tc, tr, acc);
    __syncthreads();

    // x = acc + bias; write g_x; restage x into sa; load conv0 weights
    float xr[8][4];
#pragma unroll
    for (int c = 0; c < 4; c++)
#pragma unroll
        for (int p = 0; p < 4; p++) UPK(xr[2 * p][c], xr[2 * p + 1][c], acc[c][p]);
    float4 bv = reinterpret_cast<const float4*>(pb)[tc];
    float bb[4] = {bv.x, bv.y, bv.z, bv.w};
#pragma unroll
    for (int i = 0; i < 8; i++) {
#pragma unroll
        for (int c = 0; c < 4; c++) xr[i][c] += bb[c];
        int row = rb * 128 + tr * 8 + i;
        if (row < Nn)
            *reinterpret_cast<float4*>(&g_x[row * 64 + tc * 4]) =
                make_float4(xr[i][0], xr[i][1], xr[i][2], xr[i][3]);
    }
    {
        int m = (tc * 4) & 28;
#pragma unroll
        for (int c = 0; c < 4; c++)
#pragma unroll
            for (int i = 0; i < 8; i++)
                sa[(tc * 4 + c) * RPAD + ((tr * 8 + i) ^ m)] = xr[i][c];
    }
    load_Wdup(swd, cw0, tid);
    __syncthreads();

    // conv0
    zero_acc(acc);
    mm128(sa, swd, tc, tr, acc);
    epi_h_agg(acc, cb0, rb, tc, tr);
}

// ---------------- fused BN(l-1)+relu+residual + conv GEMM + agg-init ----------
__global__ __launch_bounds__(256) void k_gemm_bn(
    const float* __restrict__ w, const float* __restrict__ cb,
    int stats_off, const float* __restrict__ gamma,
    const float* __restrict__ beta)
{
    extern __shared__ float dsm[];
    float* sa  = dsm;
    float* swd = dsm + 64 * RPAD;
    __shared__ float s_scale[64], s_shift[64];
    const int tid = threadIdx.x, rb = blockIdx.x;
    const int tc = tid & 15, tr = tid >> 4;

    if (tid < 64) {
        const float invN = 1.0f / (float)Nn;
        float mu = g_stats[stats_off + tid] * invN;
        float var = g_stats[stats_off + 64 + tid] * invN - mu * mu;
        float sc = rsqrtf(var + BN_EPS) * gamma[tid];
        s_scale[tid] = sc;
        s_shift[tid] = beta[tid] - mu * sc;
    }
    load_Wdup(swd, w, tid);
    __syncthreads();

    // x_new = x + relu(bn(agg)); persist; stage into sa
    for (int i = tid; i < 2048; i += 256) {
        int r = i >> 4, kq = (i & 15) << 2;
        int row = rb * 128 + r;
        float4 v = make_float4(0.f, 0.f, 0.f, 0.f);
        if (row < Nn) {
            v = *reinterpret_cast<const float4*>(&g_x[row * 64 + kq]);
            float4 av = *reinterpret_cast<const float4*>(&g_agg[row * 64 + kq]);
            v.x += fmaxf(av.x * s_scale[kq + 0] + s_shift[kq + 0], 0.f);
            v.y += fmaxf(av.y * s_scale[kq + 1] + s_shift[kq + 1], 0.f);
            v.z += fmaxf(av.z * s_scale[kq + 2] + s_shift[kq + 2], 0.f);
            v.w += fmaxf(av.w * s_scale[kq + 3] + s_shift[kq + 3], 0.f);
            *reinterpret_cast<float4*>(&g_x[row * 64 + kq]) = v;
        }
        int p = r ^ (kq & 28);
        sa[(kq + 0) * RPAD + p] = v.x;
        sa[(kq + 1) * RPAD + p] = v.y;
        sa[(kq + 2) * RPAD + p] = v.z;
        sa[(kq + 3) * RPAD + p] = v.w;
    }
    __syncthreads();

    u64 acc[4][4];
    zero_acc(acc);
    mm128(sa, swd, tc, tr, acc);
    epi_h_agg(acc, cb, rb, tc, tr);
}

// ---------------- edge scatter ----------------
__global__ void k_scatter(const int* __restrict__ rowi, const int* __restrict__ coli)
{
    int t = blockIdx.x * blockDim.x + threadIdx.x;
    int e = t >> 4;
    if (e >= Ee) return;
    int f = (t & 15) << 2;
    int r = __ldg(rowi + e);
    int c = __ldg(coli + e);
    float nrm = __ldg(&g_dis[r]) * __ldg(&g_dis[c]);
    float4 hv = *reinterpret_cast<const float4*>(&g_h[r * HID + f]);
    float* dst = &g_agg[c * HID + f];
    asm volatile("red.global.add.v4.f32 [%0], {%1,%2,%3,%4};"
                 :: "l"(dst), "f"(nrm * hv.x), "f"(nrm * hv.y),
                    "f"(nrm * hv.z), "f"(nrm * hv.w)
                 : "memory");
}

// ---------------- BN stats ----------------
__global__ __launch_bounds__(256) void k_stats(int stats_off)
{
    const int tid = threadIdx.x;
    const int cq = (tid & 15) * 4, rl = tid >> 4;
    float4 s  = make_float4(0.f, 0.f, 0.f, 0.f);
    float4 s2 = make_float4(0.f, 0.f, 0.f, 0.f);
    for (int row = blockIdx.x * 16 + rl; row < Nn; row += gridDim.x * 16) {
        float4 v = *reinterpret_cast<const float4*>(&g_agg[row * 64 + cq]);
        s.x += v.x; s.y += v.y; s.z += v.z; s.w += v.w;
        s2.x += v.x * v.x; s2.y += v.y * v.y; s2.z += v.z * v.z; s2.w += v.w * v.w;
    }
    __shared__ float4 ss[16][16], ss2[16][16];
    ss[rl][tid & 15] = s;
    ss2[rl][tid & 15] = s2;
    __syncthreads();
    if (rl == 0) {
        float4 a = ss[0][tid & 15], b = ss2[0][tid & 15];
#pragma unroll
        for (int k = 1; k < 16; k++) {
            float4 u = ss[k][tid & 15], v = ss2[k][tid & 15];
            a.x += u.x; a.y += u.y; a.z += u.z; a.w += u.w;
            b.x += v.x; b.y += v.y; b.z += v.z; b.w += v.w;
        }
        float* so = g_stats + stats_off;
        atomicAdd(&so[cq + 0], a.x); atomicAdd(&so[cq + 1], a.y);
        atomicAdd(&so[cq + 2], a.z); atomicAdd(&so[cq + 3], a.w);
        atomicAdd(&so[64 + cq + 0], b.x); atomicAdd(&so[64 + cq + 1], b.y);
        atomicAdd(&so[64 + cq + 2], b.z); atomicAdd(&so[64 + cq + 3], b.w);
    }
}

// ---------------- decoder fused with final BN apply ----------------
// z[n] = x[n] + relu(bn1(agg[n])); out[e] = dot(z[a], z[b])
__global__ __launch_bounds__(256) void k_decode(
    const int* __restrict__ pe, const float* __restrict__ gamma,
    const float* __restrict__ beta, float* __restrict__ out)
{
    __shared__ float ssc[64], ssh[64];
    int tid = threadIdx.x;
    if (tid < 64) {
        const float invN = 1.0f / (float)Nn;
        float mu = g_stats[128 + tid] * invN;
        float var = g_stats[192 + tid] * invN - mu * mu;
        float sc = rsqrtf(var + BN_EPS) * gamma[tid];
        ssc[tid] = sc;
        ssh[tid] = beta[tid] - mu * sc;
    }
    __syncthreads();
    int t = blockIdx.x * 256 + tid;
    int e = t >> 3, sub = t & 7;
    if (e >= EPn) return;
    int a = __ldg(pe + 2 * e);
    int b = __ldg(pe + 2 * e + 1);
    int cq = sub * 8;

    float4 xa0 = *reinterpret_cast<const float4*>(&g_x[a * 64 + cq]);
    float4 xa1 = *reinterpret_cast<const float4*>(&g_x[a * 64 + cq + 4]);
    float4 ga0 = *reinterpret_cast<const float4*>(&g_agg[a * 64 + cq]);
    float4 ga1 = *reinterpret_cast<const float4*>(&g_agg[a * 64 + cq + 4]);
    float4 xb0 = *reinterpret_cast<const float4*>(&g_x[b * 64 + cq]);
    float4 xb1 = *reinterpret_cast<const float4*>(&g_x[b * 64 + cq + 4]);
    float4 gb0 = *reinterpret_cast<const float4*>(&g_agg[b * 64 + cq]);
    float4 gb1 = *reinterpret_cast<const float4*>(&g_agg[b * 64 + cq + 4]);

    float za[8], zb[8];
    za[0] = xa0.x + fmaxf(ga0.x * ssc[cq+0] + ssh[cq+0], 0.f);
    za[1] = xa0.y + fmaxf(ga0.y * ssc[cq+1] + ssh[cq+1], 0.f);
    za[2] = xa0.z + fmaxf(ga0.z * ssc[cq+2] + ssh[cq+2], 0.f);
    za[3] = xa0.w + fmaxf(ga0.w * ssc[cq+3] + ssh[cq+3], 0.f);
    za[4] = xa1.x + fmaxf(ga1.x * ssc[cq+4] + ssh[cq+4], 0.f);
    za[5] = xa1.y + fmaxf(ga1.y * ssc[cq+5] + ssh[cq+5], 0.f);
    za[6] = xa1.z + fmaxf(ga1.z * ssc[cq+6] + ssh[cq+6], 0.f);
    za[7] = xa1.w + fmaxf(ga1.w * ssc[cq+7] + ssh[cq+7], 0.f);
    zb[0] = xb0.x + fmaxf(gb0.x * ssc[cq+0] + ssh[cq+0], 0.f);
    zb[1] = xb0.y + fmaxf(gb0.y * ssc[cq+1] + ssh[cq+1], 0.f);
    zb[2] = xb0.z + fmaxf(gb0.z * ssc[cq+2] + ssh[cq+2], 0.f);
    zb[3] = xb0.w + fmaxf(gb0.w * ssc[cq+3] + ssh[cq+3], 0.f);
    zb[4] = xb1.x + fmaxf(gb1.x * ssc[cq+4] + ssh[cq+4], 0.f);
    zb[5] = xb1.y + fmaxf(gb1.y * ssc[cq+5] + ssh[cq+5], 0.f);
    zb[6] = xb1.z + fmaxf(gb1.z * ssc[cq+6] + ssh[cq+6], 0.f);
    zb[7] = xb1.w + fmaxf(gb1.w * ssc[cq+7] + ssh[cq+7], 0.f);

    float acc = 0.f;
#pragma unroll
    for (int i = 0; i < 8; i++) acc += za[i] * zb[i];
    acc += __shfl_xor_sync(0xffffffffu, acc, 4);
    acc += __shfl_xor_sync(0xffffffffu, acc, 2);
    acc += __shfl_xor_sync(0xffffffffu, acc, 1);
    if (sub == 0) out[e] = acc;
}

// ---------------- launch ----------------
extern "C" void kernel_launch(void* const* d_in, const int* in_sizes, int n_in,
                              void* d_out, int out_size)
{
    const int*   edge   = (const int*)d_in[0];
    const int*   rowi   = edge;
    const int*   coli   = edge + Ee;
    const int*   pe     = (const int*)d_in[1];
    const float* id_emb = (const float*)d_in[2];
    const float* n2v    = (const float*)d_in[3];
    const float* pw     = (const float*)d_in[4];
    const float* pb     = (const float*)d_in[5];
    const float* cw     = (const float*)d_in[6];
    const float* cb     = (const float*)d_in[7];
    const float* gamma  = (const float*)d_in[8];
    const float* beta   = (const float*)d_in[9];
    float*       out    = (float*)d_out;

    const int TB = 256;
    const int DSM = (64 * RPAD + 64 * 128) * 4;   // 66560 bytes
    cudaFuncSetAttribute(k_proj_gemm0, cudaFuncAttributeMaxDynamicSharedMemorySize, DSM);
    cudaFuncSetAttribute(k_gemm_bn,    cudaFuncAttributeMaxDynamicSharedMemorySize, DSM);

    const int GB = (Nn + 127) / 128;   // 391 blocks, single wave

    k_deg_init <<<(Nn + TB - 1) / TB, TB>>>();
    k_deg_count<<<(Ee + TB - 1) / TB, TB>>>(coli);
    k_deg_rsqrt<<<(Nn + TB - 1) / TB, TB>>>();

    // layer 0 (fused with projection)
    k_proj_gemm0<<<GB, 256, DSM>>>(id_emb, n2v, pw, pb, cw, cb);
    k_scatter   <<<(Ee * 16 + TB - 1) / TB, TB>>>(rowi, coli);
    k_stats     <<<128, 256>>>(0);

    // layer 1 (BN-l0 fused into A-load)
    k_gemm_bn<<<GB, 256, DSM>>>(cw + HID * HID, cb + HID, 0, gamma, beta);
    k_scatter<<<(Ee * 16 + TB - 1) / TB, TB>>>(rowi, coli);
    k_stats  <<<128, 256>>>(2 * HID);

    // final BN fused into decoder
    k_decode<<<(EPn * 8 + TB - 1) / TB, TB>>>(pe, gamma + HID, beta + HID, out);
}